// round 2
// baseline (speedup 1.0000x reference)
#include <cuda_runtime.h>
#include <math.h>

#define Bn 8
#define C 128
#define HW 16384
#define Ncls 16
#define EPSF 1e-7f
#define NQ 39   // 0:nxr2 1:dsa 2:s2v 3:csum 4:wr_s 5:wsa_s 6:wo_s 7..22:rel[n] 23..38:P[n]

// ---------------- scratch (no allocations allowed) ----------------
__device__ float g_G[Bn*C*C];      // per-batch Gram x x^T
__device__ float g_sx[Bn*C];       // per-batch channel sums
__device__ float g_H[Bn*3*C*C];    // H_m = G @ W_m^T  for m in {Wr, Wsa, Wo}
__device__ float g_M[Bn*C*C];      // fused output matrix (sigma*A*Wo + I)
__device__ float g_d[Bn*C];        // fused output bias
__device__ float g_red[Bn*NQ*C];   // per-(b,c) reduction scratch
__device__ float g_u[C];           // colsum of Wsa

// ---------------- zero scratch + compute u ----------------
__global__ void zero_kernel(const float* __restrict__ Wsa) {
    int i = blockIdx.x * blockDim.x + threadIdx.x;
    if (i < Bn*C*C)  g_G[i] = 0.f;
    if (i < Bn*C)    g_sx[i] = 0.f;
    if (i < Bn*NQ*C) g_red[i] = 0.f;
    if (blockIdx.x == 0 && threadIdx.x < C) {
        float u = 0.f;
        #pragma unroll 4
        for (int r = 0; r < C; r++) u += Wsa[r*C + threadIdx.x];
        g_u[threadIdx.x] = u;
    }
}

// ---------------- Gram: G[b] = x[b] @ x[b]^T, sx[b] = rowsum ----------------
__global__ __launch_bounds__(256) void gram_kernel(const float* __restrict__ x) {
    const int b  = blockIdx.y;
    const int p0 = blockIdx.x * 512;
    const float* xb = x + b * (C * HW);
    __shared__ float xs[C][33];
    const int tid = threadIdx.x;
    const int tx = tid & 15, ty = tid >> 4;
    const int kk = tid & 31, c0 = tid >> 5;

    float accA[4][4] = {}, accB[4][4] = {}, accC[4][4] = {}, accD[4][4] = {};
    float ssum = 0.f;

    for (int kt = 0; kt < 512; kt += 32) {
        #pragma unroll
        for (int i = 0; i < 16; i++) {
            int c = c0 + i * 8;
            xs[c][kk] = xb[c * HW + p0 + kt + kk];
        }
        __syncthreads();
        #pragma unroll 4
        for (int k = 0; k < 32; k++) {
            float a0[4], a1[4], b0[4], b1[4];
            #pragma unroll
            for (int i = 0; i < 4; i++) { a0[i] = xs[ty*4+i][k];    a1[i] = xs[64+ty*4+i][k]; }
            #pragma unroll
            for (int j = 0; j < 4; j++) { b0[j] = xs[tx*4+j][k];    b1[j] = xs[64+tx*4+j][k]; }
            #pragma unroll
            for (int i = 0; i < 4; i++)
                #pragma unroll
                for (int j = 0; j < 4; j++) {
                    accA[i][j] = fmaf(a0[i], b0[j], accA[i][j]);
                    accB[i][j] = fmaf(a0[i], b1[j], accB[i][j]);
                    accC[i][j] = fmaf(a1[i], b0[j], accC[i][j]);
                    accD[i][j] = fmaf(a1[i], b1[j], accD[i][j]);
                }
        }
        if (tid < C) {
            #pragma unroll 8
            for (int k = 0; k < 32; k++) ssum += xs[tid][k];
        }
        __syncthreads();
    }

    float* Gb = g_G + b * C * C;
    #pragma unroll
    for (int i = 0; i < 4; i++) {
        int r0 = ty*4 + i, r1 = 64 + ty*4 + i;
        #pragma unroll
        for (int j = 0; j < 4; j++) {
            int q0 = tx*4 + j, q1 = 64 + tx*4 + j;
            atomicAdd(&Gb[r0*C + q0], accA[i][j]);
            atomicAdd(&Gb[r0*C + q1], accB[i][j]);
            atomicAdd(&Gb[r1*C + q0], accC[i][j]);
            atomicAdd(&Gb[r1*C + q1], accD[i][j]);
        }
    }
    if (tid < C) atomicAdd(&g_sx[b*C + tid], ssum);
}

// ---------------- H_m[b] = G[b] @ W_m^T ----------------
__global__ __launch_bounds__(256) void hgemm_kernel(const float* __restrict__ Wr,
                                                    const float* __restrict__ Wsa,
                                                    const float* __restrict__ Wo) {
    const int m = blockIdx.x;
    const int b = blockIdx.y;
    const float* W = (m == 0) ? Wr : (m == 1) ? Wsa : Wo;
    const float* G = g_G + b * C * C;
    float* H = g_H + (b * 3 + m) * C * C;

    __shared__ float As[C][33];
    __shared__ float Bs[C][33];
    const int tid = threadIdx.x;
    const int tx = tid & 15, ty = tid >> 4;
    const int kk = tid & 31, r0w = tid >> 5;

    float accA[4][4] = {}, accB[4][4] = {}, accC[4][4] = {}, accD[4][4] = {};

    for (int k0 = 0; k0 < C; k0 += 32) {
        #pragma unroll
        for (int i = 0; i < 16; i++) {
            int r = r0w + i * 8;
            As[r][kk] = G[r*C + k0 + kk];
            Bs[r][kk] = W[r*C + k0 + kk];
        }
        __syncthreads();
        #pragma unroll 4
        for (int k = 0; k < 32; k++) {
            float a0[4], a1[4], b0[4], b1[4];
            #pragma unroll
            for (int i = 0; i < 4; i++) { a0[i] = As[ty*4+i][k]; a1[i] = As[64+ty*4+i][k]; }
            #pragma unroll
            for (int j = 0; j < 4; j++) { b0[j] = Bs[tx*4+j][k]; b1[j] = Bs[64+tx*4+j][k]; }
            #pragma unroll
            for (int i = 0; i < 4; i++)
                #pragma unroll
                for (int j = 0; j < 4; j++) {
                    accA[i][j] = fmaf(a0[i], b0[j], accA[i][j]);
                    accB[i][j] = fmaf(a0[i], b1[j], accB[i][j]);
                    accC[i][j] = fmaf(a1[i], b0[j], accC[i][j]);
                    accD[i][j] = fmaf(a1[i], b1[j], accD[i][j]);
                }
        }
        __syncthreads();
    }

    #pragma unroll
    for (int i = 0; i < 4; i++) {
        int r0 = ty*4 + i, r1 = 64 + ty*4 + i;
        #pragma unroll
        for (int j = 0; j < 4; j++) {
            int q0 = tx*4 + j, q1 = 64 + tx*4 + j;
            H[r0*C + q0] = accA[i][j];
            H[r0*C + q1] = accB[i][j];
            H[r1*C + q0] = accC[i][j];
            H[r1*C + q1] = accD[i][j];
        }
    }
}

// ---------------- reduce: 39 per-(b,c) reductions over i, split 8 ways ----------------
// grid (Bn, 8), block 128. Block covers i in [seg*16, seg*16+16).
__global__ __launch_bounds__(128) void reduce_kernel(
    const float* __restrict__ Wr, const float* __restrict__ Wsa,
    const float* __restrict__ Wo, const float* __restrict__ kn)
{
    const int b   = blockIdx.x;
    const int i0  = blockIdx.y * 16;
    const int c   = threadIdx.x;
    const float* G  = g_G + b*C*C;
    const float* Hr = g_H + (b*3 + 0)*C*C;
    const float* Hs = g_H + (b*3 + 1)*C*C;
    const float* Ho = g_H + (b*3 + 2)*C*C;

    __shared__ float kn_s[16][Ncls];
    __shared__ float s_s[16], u_s[16];
    {
        int t = threadIdx.x;           // 0..127
        int n = t & 15, ii = t >> 4;   // covers ii 0..7
        kn_s[ii][n]     = kn[n*C + i0 + ii];
        kn_s[ii + 8][n] = kn[n*C + i0 + ii + 8];
        if (t < 16) { s_s[t] = g_sx[b*C + i0 + t]; u_s[t] = g_u[i0 + t]; }
    }
    __syncthreads();

    float nxr2 = 0.f, dsa = 0.f, s2v = 0.f, csum = 0.f;
    float wr_s = 0.f, wsa_s = 0.f, wo_s = 0.f;
    float rel[Ncls], P[Ncls];
    #pragma unroll
    for (int n = 0; n < Ncls; n++) { rel[n] = 0.f; P[n] = 0.f; }

    #pragma unroll 4
    for (int ii = 0; ii < 16; ii++) {
        const int i = i0 + ii;
        float hr = Hr[i*C + c];
        float hs = Hs[i*C + c];
        float ho = Ho[i*C + c];
        float g  = G [i*C + c];
        float wri = Wr[c*C + i], wsi = Wsa[c*C + i], woi = Wo[c*C + i];
        float si = s_s[ii], ui = u_s[ii];
        nxr2 = fmaf(wri, hr, nxr2);
        dsa  = fmaf(wsi, hs, dsa);
        s2v  = fmaf(woi, ho, s2v);
        csum = fmaf(ui,  hs, csum);
        wr_s = fmaf(wri, si, wr_s);
        wsa_s= fmaf(wsi, si, wsa_s);
        wo_s = fmaf(woi, si, wo_s);
        #pragma unroll
        for (int n = 0; n < Ncls; n++) {
            float kv = kn_s[ii][n];
            rel[n] = fmaf(kv, hr, rel[n]);
            P[n]   = fmaf(kv, g,  P[n]);
        }
    }

    float* R = g_red + b*NQ*C;
    atomicAdd(&R[0*C + c], nxr2);
    atomicAdd(&R[1*C + c], dsa);
    atomicAdd(&R[2*C + c], s2v);
    atomicAdd(&R[3*C + c], csum);
    atomicAdd(&R[4*C + c], wr_s);
    atomicAdd(&R[5*C + c], wsa_s);
    atomicAdd(&R[6*C + c], wo_s);
    #pragma unroll
    for (int n = 0; n < Ncls; n++) {
        atomicAdd(&R[(7 + n)*C + c],  rel[n]);
        atomicAdd(&R[(23 + n)*C + c], P[n]);
    }
}

// ---------------- finalize: softmaxes + group stats -> M, d ----------------
// grid Bn, block 128
__global__ __launch_bounds__(128) void finalize_kernel(
    const float* __restrict__ bsa, const float* __restrict__ br,
    const float* __restrict__ kn,
    const float* __restrict__ Wo,  const float* __restrict__ bo,
    const float* __restrict__ alpha, const float* __restrict__ sigma)
{
    const int b = blockIdx.x;
    const int c = threadIdx.x;
    const float* R = g_red + b*NQ*C;
    const float hwf = 16384.f;

    __shared__ float s_sh[C], m_sh[C], s1_sh[C], s2_sh[C], A_sh[C], red_s[C];
    __shared__ float att_sh[Ncls][C];
    __shared__ float pn_sh[Ncls][C];
    __shared__ float nxn_sh[Ncls], kns_sh[Ncls], inv_sh[Ncls], minv_sh[Ncls];
    __shared__ float sc_us, sc_sb, sc_mx, sc_sum;

    float s_c = g_sx[b*C + c];
    s_sh[c] = s_c;
    float u_c = g_u[c];
    float bsc = bsa[c], brc = br[c], boc = bo[c];

    // block reduce: us = u.s, sb = sum(bsa)
    red_s[c] = u_c * s_c;
    __syncthreads();
    #pragma unroll
    for (int s = 64; s > 0; s >>= 1) { if (c < s) red_s[c] += red_s[c + s]; __syncthreads(); }
    if (c == 0) sc_us = red_s[0];
    __syncthreads();
    red_s[c] = bsc;
    __syncthreads();
    #pragma unroll
    for (int s = 64; s > 0; s >>= 1) { if (c < s) red_s[c] += red_s[c + s]; __syncthreads(); }
    if (c == 0) sc_sb = red_s[0];
    __syncthreads();

    // nxn[n] = sqrt(sum_c P[n][c]*kn[n][c])
    #pragma unroll
    for (int n = 0; n < Ncls; n++) pn_sh[n][c] = R[(23 + n)*C + c] * kn[n*C + c];
    __syncthreads();
    if (c < Ncls) {
        float t = 0.f;
        #pragma unroll 4
        for (int k = 0; k < C; k++) t += pn_sh[c][k];
        nxn_sh[c] = sqrtf(t);
    }
    __syncthreads();
    // kns[n] = kn[n] . s
    #pragma unroll
    for (int n = 0; n < Ncls; n++) pn_sh[n][c] = kn[n*C + c] * s_sh[c];
    __syncthreads();
    if (c < Ncls) {
        float t = 0.f;
        #pragma unroll 4
        for (int k = 0; k < C; k++) t += pn_sh[c][k];
        kns_sh[c] = t;
    }
    __syncthreads();

    // per-channel scalars
    float wr_s = R[4*C + c], wsa_s = R[5*C + c], wo_s = R[6*C + c];
    float nxr2 = R[0*C + c] + 2.f*brc*wr_s + hwf*brc*brc;
    float nxr  = sqrtf(nxr2);
    float dsa  = R[1*C + c] + 2.f*bsc*wsa_s + hwf*bsc*bsc;
    float csum = R[3*C + c] + sc_sb*wsa_s + bsc*sc_us + hwf*sc_sb*bsc;
    m_sh[c]  = (csum - dsa) * (1.f/128.f);
    s1_sh[c] = wo_s + hwf*boc;
    s2_sh[c] = R[2*C + c] + 2.f*boc*wo_s + hwf*boc*boc;
    __syncthreads();

    // regular = softmax over c of m (block max + sum)
    red_s[c] = m_sh[c];
    __syncthreads();
    #pragma unroll
    for (int s = 64; s > 0; s >>= 1) { if (c < s) red_s[c] = fmaxf(red_s[c], red_s[c + s]); __syncthreads(); }
    if (c == 0) sc_mx = red_s[0];
    __syncthreads();
    float ex = expf(m_sh[c] - sc_mx);
    red_s[c] = ex;
    __syncthreads();
    #pragma unroll
    for (int s = 64; s > 0; s >>= 1) { if (c < s) red_s[c] += red_s[c + s]; __syncthreads(); }
    if (c == 0) sc_sum = red_s[0];
    __syncthreads();
    float regular = ex / sc_sum;

    // att = softmax over n of relation_norm + alpha*regular
    {
        float rn[Ncls];
        float mxn = -1e30f;
        #pragma unroll
        for (int n = 0; n < Ncls; n++) {
            float r = R[(7 + n)*C + c] + brc * kns_sh[n];
            float al = fminf(fmaxf(alpha[n], 0.f), 1.f);
            rn[n] = r / (nxn_sh[n]*nxr + EPSF) + al * regular;
            mxn = fmaxf(mxn, rn[n]);
        }
        float se = 0.f;
        #pragma unroll
        for (int n = 0; n < Ncls; n++) { rn[n] = expf(rn[n] - mxn); se += rn[n]; }
        float ise = 1.f / se;
        #pragma unroll
        for (int n = 0; n < Ncls; n++) att_sh[n][c] = rn[n] * ise;
    }
    __syncthreads();

    // per-class group-norm stats
    if (c < Ncls) {
        int n = c;
        float cnt = 0.f, hot = 0.f, sq2 = 0.f;
        #pragma unroll 4
        for (int cc = 0; cc < C; cc++) {
            float a = att_sh[n][cc];
            cnt += a;
            hot = fmaf(a, s1_sh[cc], hot);
            sq2 = fmaf(a*a, s2_sh[cc], sq2);
        }
        cnt = cnt * hwf + EPSF;
        float mean = hot / cnt;
        float sq = sq2 - 2.f*mean*hot + mean*mean*(128.f*hwf);
        float stdv = sqrtf(sq / cnt);
        float inv = 1.f / (stdv + EPSF);
        inv_sh[n] = inv; minv_sh[n] = mean * inv;
    }
    __syncthreads();

    // A, B, d
    float sg = sigma[0];
    {
        float Av = 0.f, Bv = 0.f;
        #pragma unroll
        for (int n = 0; n < Ncls; n++) {
            float a = att_sh[n][c];
            Av = fmaf(a, inv_sh[n],  Av);
            Bv = fmaf(a, minv_sh[n], Bv);
        }
        A_sh[c] = Av;
        g_d[b*C + c] = sg * (Av * boc - Bv);
    }
    __syncthreads();

    // M = sigma*diag(A)*Wo + I
    #pragma unroll 4
    for (int t = c; t < C*C; t += 128) {
        int o = t >> 7, cc = t & 127;
        float v = sg * A_sh[o] * Wo[t];
        if (o == cc) v += 1.f;
        g_M[b*C*C + t] = v;
    }
}

// ---------------- orthogonality loss ----------------
__global__ void loss_kernel(const float* __restrict__ kn, float* __restrict__ out, int out_size) {
    __shared__ float sym[Ncls][Ncls];
    __shared__ float partial[256];
    int tid = threadIdx.x;
    int i = tid >> 4, j = tid & 15;
    float dot = 0.f;
    #pragma unroll 4
    for (int k = 0; k < C; k++) dot = fmaf(kn[i*C + k], kn[j*C + k], dot);
    sym[i][j] = dot;
    __syncthreads();
    float nr = sqrtf(sym[i][i]) * sqrtf(sym[j][j]);
    float l = sym[i][j] / (nr + EPSF) - (i == j ? 1.f : 0.f);
    partial[tid] = l * l;
    __syncthreads();
    for (int s = 128; s > 0; s >>= 1) {
        if (tid < s) partial[tid] += partial[tid + s];
        __syncthreads();
    }
    if (tid == 0) {
        float loss = 0.1f * logf(partial[0] + 1.f);
        for (int idx = Bn*C*HW; idx < out_size; idx++) out[idx] = loss;
    }
}

// ---------------- out = M[b] @ x[b] + d[b] ----------------
__global__ __launch_bounds__(256) void out_kernel(const float* __restrict__ x,
                                                  float* __restrict__ out) {
    const int b  = blockIdx.y;
    const int p0 = blockIdx.x * 128;
    const float* Mb = g_M + b*C*C;
    const float* xb = x + b * (C * HW);
    float* ob = out + b * (C * HW);

    __shared__ float Ms[C][33];
    __shared__ float xsh[32][132];
    const int tid = threadIdx.x;
    const int tx = tid & 15, ty = tid >> 4;

    float accA[4][4] = {}, accB[4][4] = {}, accC[4][4] = {}, accD[4][4] = {};

    for (int k0 = 0; k0 < C; k0 += 32) {
        {
            int kk = tid & 31, o0 = tid >> 5;
            #pragma unroll
            for (int i = 0; i < 16; i++) {
                int o = o0 + i * 8;
                Ms[o][kk] = Mb[o*C + k0 + kk];
            }
        }
        {
            #pragma unroll
            for (int t = 0; t < 4; t++) {
                int idx = tid + t * 256;
                int kk = idx >> 5, pp = (idx & 31) * 4;
                float4 v = *reinterpret_cast<const float4*>(&xb[(k0 + kk)*HW + p0 + pp]);
                *reinterpret_cast<float4*>(&xsh[kk][pp]) = v;
            }
        }
        __syncthreads();
        #pragma unroll 4
        for (int k = 0; k < 32; k++) {
            float a0[4], a1[4];
            #pragma unroll
            for (int i = 0; i < 4; i++) { a0[i] = Ms[ty*4+i][k]; a1[i] = Ms[64+ty*4+i][k]; }
            float4 bv0 = *reinterpret_cast<const float4*>(&xsh[k][tx*4]);
            float4 bv1 = *reinterpret_cast<const float4*>(&xsh[k][64 + tx*4]);
            float b0[4] = {bv0.x, bv0.y, bv0.z, bv0.w};
            float b1[4] = {bv1.x, bv1.y, bv1.z, bv1.w};
            #pragma unroll
            for (int i = 0; i < 4; i++)
                #pragma unroll
                for (int j = 0; j < 4; j++) {
                    accA[i][j] = fmaf(a0[i], b0[j], accA[i][j]);
                    accB[i][j] = fmaf(a0[i], b1[j], accB[i][j]);
                    accC[i][j] = fmaf(a1[i], b0[j], accC[i][j]);
                    accD[i][j] = fmaf(a1[i], b1[j], accD[i][j]);
                }
        }
        __syncthreads();
    }

    #pragma unroll
    for (int i = 0; i < 4; i++) {
        int o0 = ty*4 + i, o1 = 64 + ty*4 + i;
        float d0 = g_d[b*C + o0], d1 = g_d[b*C + o1];
        float4 v;
        v.x = accA[i][0] + d0; v.y = accA[i][1] + d0; v.z = accA[i][2] + d0; v.w = accA[i][3] + d0;
        *reinterpret_cast<float4*>(&ob[o0*HW + p0 + tx*4]) = v;
        v.x = accB[i][0] + d0; v.y = accB[i][1] + d0; v.z = accB[i][2] + d0; v.w = accB[i][3] + d0;
        *reinterpret_cast<float4*>(&ob[o0*HW + p0 + 64 + tx*4]) = v;
        v.x = accC[i][0] + d1; v.y = accC[i][1] + d1; v.z = accC[i][2] + d1; v.w = accC[i][3] + d1;
        *reinterpret_cast<float4*>(&ob[o1*HW + p0 + tx*4]) = v;
        v.x = accD[i][0] + d1; v.y = accD[i][1] + d1; v.z = accD[i][2] + d1; v.w = accD[i][3] + d1;
        *reinterpret_cast<float4*>(&ob[o1*HW + p0 + 64 + tx*4]) = v;
    }
}

extern "C" void kernel_launch(void* const* d_in, const int* in_sizes, int n_in,
                              void* d_out, int out_size) {
    const float* x     = (const float*)d_in[0];
    const float* Wsa   = (const float*)d_in[1];
    const float* bsa   = (const float*)d_in[2];
    const float* Wr    = (const float*)d_in[3];
    const float* br    = (const float*)d_in[4];
    const float* kn    = (const float*)d_in[5];
    const float* Wo    = (const float*)d_in[6];
    const float* bo    = (const float*)d_in[7];
    const float* alpha = (const float*)d_in[8];
    const float* sigma = (const float*)d_in[9];
    float* out = (float*)d_out;

    zero_kernel<<<(Bn*C*C + 255) / 256, 256>>>(Wsa);
    gram_kernel<<<dim3(32, Bn), 256>>>(x);
    hgemm_kernel<<<dim3(3, Bn), 256>>>(Wr, Wsa, Wo);
    reduce_kernel<<<dim3(Bn, 8), 128>>>(Wr, Wsa, Wo, kn);
    finalize_kernel<<<Bn, 128>>>(bsa, br, kn, Wo, bo, alpha, sigma);
    loss_kernel<<<1, 256>>>(kn, out, out_size);
    out_kernel<<<dim3(128, Bn), 256>>>(x, out);
}

// round 3
// speedup vs baseline: 1.5970x; 1.5970x over previous
#include <cuda_runtime.h>
#include <math.h>

#define Bn 8
#define C 128
#define HW 16384
#define Ncls 16
#define EPSF 1e-7f
#define NQ 39

typedef unsigned long long ull;

// packed f32x2 helpers (sm_103a)
#define FMA_F32X2(d, a, b) \
    asm("fma.rn.f32x2 %0, %1, %2, %0;" : "+l"(d) : "l"(a), "l"(b))
#define PACK_DUP(d, s) \
    asm("mov.b64 %0, {%1, %1};" : "=l"(d) : "r"(__float_as_uint(s)))

// ---------------- scratch ----------------
__device__ float g_G[Bn*C*C];
__device__ float g_sx[Bn*C];
__device__ float g_H[Bn*3*C*C];
__device__ float g_M[Bn*C*C];
__device__ float g_d[Bn*C];
__device__ float g_red[Bn*NQ*C];
__device__ float g_u[C];

// ---------------- zero scratch + compute u ----------------
__global__ void zero_kernel(const float* __restrict__ Wsa) {
    int i = blockIdx.x * blockDim.x + threadIdx.x;
    if (i < Bn*C*C)  g_G[i] = 0.f;
    if (i < Bn*C)    g_sx[i] = 0.f;
    if (i < Bn*NQ*C) g_red[i] = 0.f;
    if (blockIdx.x == 0 && threadIdx.x < C) {
        float u = 0.f;
        #pragma unroll 4
        for (int r = 0; r < C; r++) u += Wsa[r*C + threadIdx.x];
        g_u[threadIdx.x] = u;
    }
}

// ---------------- Gram: G[b] = x[b] @ x[b]^T (f32x2 packed) ----------------
// grid (16, Bn): 16 pixel-chunks of 1024. block 256: tx=tid&15, ty=tid>>4, 8x8 per thread.
__global__ __launch_bounds__(256) void gram_kernel(const float* __restrict__ x) {
    const int b  = blockIdx.y;
    const int p0 = blockIdx.x * 1024;
    const float* xb = x + b * (C * HW);
    __shared__ float xs[32][130];   // [k][c], stride 130 (2-way write conflict, 8B aligned rows)
    const int tid = threadIdx.x;
    const int tx = tid & 15, ty = tid >> 4;
    const int kk = tid & 31, c0 = tid >> 5;

    ull acc2[8][4];
    #pragma unroll
    for (int i = 0; i < 8; i++)
        #pragma unroll
        for (int p = 0; p < 4; p++) acc2[i][p] = 0ull;
    float ssum = 0.f;

    for (int kt = 0; kt < 1024; kt += 32) {
        #pragma unroll
        for (int i = 0; i < 16; i++) {
            int c = c0 + i * 8;
            xs[kk][c] = xb[c * HW + p0 + kt + kk];
        }
        __syncthreads();
        #pragma unroll 4
        for (int k = 0; k < 32; k++) {
            ull b2[4];
            b2[0] = *(const ull*)&xs[k][tx*4];
            b2[1] = *(const ull*)&xs[k][tx*4 + 2];
            b2[2] = *(const ull*)&xs[k][64 + tx*4];
            b2[3] = *(const ull*)&xs[k][64 + tx*4 + 2];
            float2 av0 = *(const float2*)&xs[k][ty*4];
            float2 av1 = *(const float2*)&xs[k][ty*4 + 2];
            float2 av2 = *(const float2*)&xs[k][64 + ty*4];
            float2 av3 = *(const float2*)&xs[k][64 + ty*4 + 2];
            ull a2[8];
            PACK_DUP(a2[0], av0.x); PACK_DUP(a2[1], av0.y);
            PACK_DUP(a2[2], av1.x); PACK_DUP(a2[3], av1.y);
            PACK_DUP(a2[4], av2.x); PACK_DUP(a2[5], av2.y);
            PACK_DUP(a2[6], av3.x); PACK_DUP(a2[7], av3.y);
            #pragma unroll
            for (int i = 0; i < 8; i++)
                #pragma unroll
                for (int p = 0; p < 4; p++)
                    FMA_F32X2(acc2[i][p], a2[i], b2[p]);
        }
        if (tid < C) {
            #pragma unroll 8
            for (int k = 0; k < 32; k++) ssum += xs[k][tid];
        }
        __syncthreads();
    }

    float* Gb = g_G + b * C * C;
    #pragma unroll
    for (int i = 0; i < 8; i++) {
        int r = (i < 4) ? (ty*4 + i) : (64 + ty*4 + (i - 4));
        #pragma unroll
        for (int p = 0; p < 4; p++) {
            int q = (p < 2) ? (tx*4 + 2*p) : (64 + tx*4 + 2*(p - 2));
            float2 v = *(float2*)&acc2[i][p];
            atomicAdd(&Gb[r*C + q],     v.x);
            atomicAdd(&Gb[r*C + q + 1], v.y);
        }
    }
    if (tid < C) atomicAdd(&g_sx[b*C + tid], ssum);
}

// ---------------- H_m[b] = G[b] @ W_m^T ----------------
__global__ __launch_bounds__(256) void hgemm_kernel(const float* __restrict__ Wr,
                                                    const float* __restrict__ Wsa,
                                                    const float* __restrict__ Wo) {
    const int m = blockIdx.x;
    const int b = blockIdx.y;
    const float* W = (m == 0) ? Wr : (m == 1) ? Wsa : Wo;
    const float* G = g_G + b * C * C;
    float* H = g_H + (b * 3 + m) * C * C;

    __shared__ float As[C][33];
    __shared__ float Bs[C][33];
    const int tid = threadIdx.x;
    const int tx = tid & 15, ty = tid >> 4;
    const int kk = tid & 31, r0w = tid >> 5;

    float accA[4][4] = {}, accB[4][4] = {}, accC[4][4] = {}, accD[4][4] = {};

    for (int k0 = 0; k0 < C; k0 += 32) {
        #pragma unroll
        for (int i = 0; i < 16; i++) {
            int r = r0w + i * 8;
            As[r][kk] = G[r*C + k0 + kk];
            Bs[r][kk] = W[r*C + k0 + kk];
        }
        __syncthreads();
        #pragma unroll 4
        for (int k = 0; k < 32; k++) {
            float a0[4], a1[4], b0[4], b1[4];
            #pragma unroll
            for (int i = 0; i < 4; i++) { a0[i] = As[ty*4+i][k]; a1[i] = As[64+ty*4+i][k]; }
            #pragma unroll
            for (int j = 0; j < 4; j++) { b0[j] = Bs[tx*4+j][k]; b1[j] = Bs[64+tx*4+j][k]; }
            #pragma unroll
            for (int i = 0; i < 4; i++)
                #pragma unroll
                for (int j = 0; j < 4; j++) {
                    accA[i][j] = fmaf(a0[i], b0[j], accA[i][j]);
                    accB[i][j] = fmaf(a0[i], b1[j], accB[i][j]);
                    accC[i][j] = fmaf(a1[i], b0[j], accC[i][j]);
                    accD[i][j] = fmaf(a1[i], b1[j], accD[i][j]);
                }
        }
        __syncthreads();
    }

    #pragma unroll
    for (int i = 0; i < 4; i++) {
        int r0 = ty*4 + i, r1 = 64 + ty*4 + i;
        #pragma unroll
        for (int j = 0; j < 4; j++) {
            int q0 = tx*4 + j, q1 = 64 + tx*4 + j;
            H[r0*C + q0] = accA[i][j];
            H[r0*C + q1] = accB[i][j];
            H[r1*C + q0] = accC[i][j];
            H[r1*C + q1] = accD[i][j];
        }
    }
}

// ---------------- reduce: 39 per-(b,c) reductions over i ----------------
__global__ __launch_bounds__(128) void reduce_kernel(
    const float* __restrict__ Wr, const float* __restrict__ Wsa,
    const float* __restrict__ Wo, const float* __restrict__ kn)
{
    const int b   = blockIdx.x;
    const int i0  = blockIdx.y * 16;
    const int c   = threadIdx.x;
    const float* G  = g_G + b*C*C;
    const float* Hr = g_H + (b*3 + 0)*C*C;
    const float* Hs = g_H + (b*3 + 1)*C*C;
    const float* Ho = g_H + (b*3 + 2)*C*C;

    __shared__ float kn_s[16][Ncls];
    __shared__ float s_s[16], u_s[16];
    {
        int t = threadIdx.x;
        int n = t & 15, ii = t >> 4;
        kn_s[ii][n]     = kn[n*C + i0 + ii];
        kn_s[ii + 8][n] = kn[n*C + i0 + ii + 8];
        if (t < 16) { s_s[t] = g_sx[b*C + i0 + t]; u_s[t] = g_u[i0 + t]; }
    }
    __syncthreads();

    float nxr2 = 0.f, dsa = 0.f, s2v = 0.f, csum = 0.f;
    float wr_s = 0.f, wsa_s = 0.f, wo_s = 0.f;
    float rel[Ncls], P[Ncls];
    #pragma unroll
    for (int n = 0; n < Ncls; n++) { rel[n] = 0.f; P[n] = 0.f; }

    #pragma unroll 4
    for (int ii = 0; ii < 16; ii++) {
        const int i = i0 + ii;
        float hr = Hr[i*C + c];
        float hs = Hs[i*C + c];
        float ho = Ho[i*C + c];
        float g  = G [i*C + c];
        float wri = Wr[c*C + i], wsi = Wsa[c*C + i], woi = Wo[c*C + i];
        float si = s_s[ii], ui = u_s[ii];
        nxr2 = fmaf(wri, hr, nxr2);
        dsa  = fmaf(wsi, hs, dsa);
        s2v  = fmaf(woi, ho, s2v);
        csum = fmaf(ui,  hs, csum);
        wr_s = fmaf(wri, si, wr_s);
        wsa_s= fmaf(wsi, si, wsa_s);
        wo_s = fmaf(woi, si, wo_s);
        #pragma unroll
        for (int n = 0; n < Ncls; n++) {
            float kv = kn_s[ii][n];
            rel[n] = fmaf(kv, hr, rel[n]);
            P[n]   = fmaf(kv, g,  P[n]);
        }
    }

    float* R = g_red + b*NQ*C;
    atomicAdd(&R[0*C + c], nxr2);
    atomicAdd(&R[1*C + c], dsa);
    atomicAdd(&R[2*C + c], s2v);
    atomicAdd(&R[3*C + c], csum);
    atomicAdd(&R[4*C + c], wr_s);
    atomicAdd(&R[5*C + c], wsa_s);
    atomicAdd(&R[6*C + c], wo_s);
    #pragma unroll
    for (int n = 0; n < Ncls; n++) {
        atomicAdd(&R[(7 + n)*C + c],  rel[n]);
        atomicAdd(&R[(23 + n)*C + c], P[n]);
    }
}

// ---------------- finalize ----------------
__global__ __launch_bounds__(128) void finalize_kernel(
    const float* __restrict__ bsa, const float* __restrict__ br,
    const float* __restrict__ kn,
    const float* __restrict__ Wo,  const float* __restrict__ bo,
    const float* __restrict__ alpha, const float* __restrict__ sigma)
{
    const int b = blockIdx.x;
    const int c = threadIdx.x;
    const float* R = g_red + b*NQ*C;
    const float hwf = 16384.f;

    __shared__ float s_sh[C], m_sh[C], s1_sh[C], s2_sh[C], A_sh[C], red_s[C];
    __shared__ float att_sh[Ncls][C];
    __shared__ float pn_sh[Ncls][C];
    __shared__ float nxn_sh[Ncls], kns_sh[Ncls], inv_sh[Ncls], minv_sh[Ncls];
    __shared__ float sc_us, sc_sb, sc_mx, sc_sum;

    float s_c = g_sx[b*C + c];
    s_sh[c] = s_c;
    float u_c = g_u[c];
    float bsc = bsa[c], brc = br[c], boc = bo[c];

    red_s[c] = u_c * s_c;
    __syncthreads();
    #pragma unroll
    for (int s = 64; s > 0; s >>= 1) { if (c < s) red_s[c] += red_s[c + s]; __syncthreads(); }
    if (c == 0) sc_us = red_s[0];
    __syncthreads();
    red_s[c] = bsc;
    __syncthreads();
    #pragma unroll
    for (int s = 64; s > 0; s >>= 1) { if (c < s) red_s[c] += red_s[c + s]; __syncthreads(); }
    if (c == 0) sc_sb = red_s[0];
    __syncthreads();

    #pragma unroll
    for (int n = 0; n < Ncls; n++) pn_sh[n][c] = R[(23 + n)*C + c] * kn[n*C + c];
    __syncthreads();
    if (c < Ncls) {
        float t = 0.f;
        #pragma unroll 4
        for (int k = 0; k < C; k++) t += pn_sh[c][k];
        nxn_sh[c] = sqrtf(t);
    }
    __syncthreads();
    #pragma unroll
    for (int n = 0; n < Ncls; n++) pn_sh[n][c] = kn[n*C + c] * s_sh[c];
    __syncthreads();
    if (c < Ncls) {
        float t = 0.f;
        #pragma unroll 4
        for (int k = 0; k < C; k++) t += pn_sh[c][k];
        kns_sh[c] = t;
    }
    __syncthreads();

    float wr_s = R[4*C + c], wsa_s = R[5*C + c], wo_s = R[6*C + c];
    float nxr2 = R[0*C + c] + 2.f*brc*wr_s + hwf*brc*brc;
    float nxr  = sqrtf(nxr2);
    float dsa  = R[1*C + c] + 2.f*bsc*wsa_s + hwf*bsc*bsc;
    float csum = R[3*C + c] + sc_sb*wsa_s + bsc*sc_us + hwf*sc_sb*bsc;
    m_sh[c]  = (csum - dsa) * (1.f/128.f);
    s1_sh[c] = wo_s + hwf*boc;
    s2_sh[c] = R[2*C + c] + 2.f*boc*wo_s + hwf*boc*boc;
    __syncthreads();

    red_s[c] = m_sh[c];
    __syncthreads();
    #pragma unroll
    for (int s = 64; s > 0; s >>= 1) { if (c < s) red_s[c] = fmaxf(red_s[c], red_s[c + s]); __syncthreads(); }
    if (c == 0) sc_mx = red_s[0];
    __syncthreads();
    float ex = expf(m_sh[c] - sc_mx);
    red_s[c] = ex;
    __syncthreads();
    #pragma unroll
    for (int s = 64; s > 0; s >>= 1) { if (c < s) red_s[c] += red_s[c + s]; __syncthreads(); }
    if (c == 0) sc_sum = red_s[0];
    __syncthreads();
    float regular = ex / sc_sum;

    {
        float rn[Ncls];
        float mxn = -1e30f;
        #pragma unroll
        for (int n = 0; n < Ncls; n++) {
            float r = R[(7 + n)*C + c] + brc * kns_sh[n];
            float al = fminf(fmaxf(alpha[n], 0.f), 1.f);
            rn[n] = r / (nxn_sh[n]*nxr + EPSF) + al * regular;
            mxn = fmaxf(mxn, rn[n]);
        }
        float se = 0.f;
        #pragma unroll
        for (int n = 0; n < Ncls; n++) { rn[n] = expf(rn[n] - mxn); se += rn[n]; }
        float ise = 1.f / se;
        #pragma unroll
        for (int n = 0; n < Ncls; n++) att_sh[n][c] = rn[n] * ise;
    }
    __syncthreads();

    if (c < Ncls) {
        int n = c;
        float cnt = 0.f, hot = 0.f, sq2 = 0.f;
        #pragma unroll 4
        for (int cc = 0; cc < C; cc++) {
            float a = att_sh[n][cc];
            cnt += a;
            hot = fmaf(a, s1_sh[cc], hot);
            sq2 = fmaf(a*a, s2_sh[cc], sq2);
        }
        cnt = cnt * hwf + EPSF;
        float mean = hot / cnt;
        float sq = sq2 - 2.f*mean*hot + mean*mean*(128.f*hwf);
        float stdv = sqrtf(sq / cnt);
        float inv = 1.f / (stdv + EPSF);
        inv_sh[n] = inv; minv_sh[n] = mean * inv;
    }
    __syncthreads();

    float sg = sigma[0];
    {
        float Av = 0.f, Bv = 0.f;
        #pragma unroll
        for (int n = 0; n < Ncls; n++) {
            float a = att_sh[n][c];
            Av = fmaf(a, inv_sh[n],  Av);
            Bv = fmaf(a, minv_sh[n], Bv);
        }
        A_sh[c] = Av;
        g_d[b*C + c] = sg * (Av * boc - Bv);
    }
    __syncthreads();

    #pragma unroll 4
    for (int t = c; t < C*C; t += 128) {
        int o = t >> 7, cc = t & 127;
        float v = sg * A_sh[o] * Wo[t];
        if (o == cc) v += 1.f;
        g_M[b*C*C + t] = v;
    }
}

// ---------------- orthogonality loss ----------------
__global__ void loss_kernel(const float* __restrict__ kn, float* __restrict__ out, int out_size) {
    __shared__ float sym[Ncls][Ncls];
    __shared__ float partial[256];
    int tid = threadIdx.x;
    int i = tid >> 4, j = tid & 15;
    float dot = 0.f;
    #pragma unroll 4
    for (int k = 0; k < C; k++) dot = fmaf(kn[i*C + k], kn[j*C + k], dot);
    sym[i][j] = dot;
    __syncthreads();
    float nr = sqrtf(sym[i][i]) * sqrtf(sym[j][j]);
    float l = sym[i][j] / (nr + EPSF) - (i == j ? 1.f : 0.f);
    partial[tid] = l * l;
    __syncthreads();
    for (int s = 128; s > 0; s >>= 1) {
        if (tid < s) partial[tid] += partial[tid + s];
        __syncthreads();
    }
    if (tid == 0) {
        float loss = 0.1f * logf(partial[0] + 1.f);
        for (int idx = Bn*C*HW; idx < out_size; idx++) out[idx] = loss;
    }
}

// ---------------- out = M[b] @ x[b] + d[b]  (f32x2 packed) ----------------
__global__ __launch_bounds__(256) void out_kernel(const float* __restrict__ x,
                                                  float* __restrict__ out) {
    const int b  = blockIdx.y;
    const int p0 = blockIdx.x * 128;
    const float* Mb = g_M + b*C*C;
    const float* xb = x + b * (C * HW);
    float* ob = out + b * (C * HW);

    __shared__ float Msh[32][130];   // [k][o]
    __shared__ float xsh[32][132];   // [k][p]
    const int tid = threadIdx.x;
    const int tx = tid & 15, ty = tid >> 4;

    ull acc2[8][4];
    #pragma unroll
    for (int i = 0; i < 8; i++)
        #pragma unroll
        for (int p = 0; p < 4; p++) acc2[i][p] = 0ull;

    for (int k0 = 0; k0 < C; k0 += 32) {
        {
            int kk = tid & 31, o0 = tid >> 5;
            #pragma unroll
            for (int i = 0; i < 16; i++) {
                int o = o0 + i * 8;
                Msh[kk][o] = Mb[o*C + k0 + kk];
            }
        }
        {
            #pragma unroll
            for (int t = 0; t < 4; t++) {
                int idx = tid + t * 256;
                int kk = idx >> 5, pp = (idx & 31) * 4;
                float4 v = *reinterpret_cast<const float4*>(&xb[(k0 + kk)*HW + p0 + pp]);
                *reinterpret_cast<float4*>(&xsh[kk][pp]) = v;
            }
        }
        __syncthreads();
        #pragma unroll 4
        for (int k = 0; k < 32; k++) {
            ull b2[4];
            b2[0] = *(const ull*)&xsh[k][tx*4];
            b2[1] = *(const ull*)&xsh[k][tx*4 + 2];
            b2[2] = *(const ull*)&xsh[k][64 + tx*4];
            b2[3] = *(const ull*)&xsh[k][64 + tx*4 + 2];
            float2 av0 = *(const float2*)&Msh[k][ty*4];
            float2 av1 = *(const float2*)&Msh[k][ty*4 + 2];
            float2 av2 = *(const float2*)&Msh[k][64 + ty*4];
            float2 av3 = *(const float2*)&Msh[k][64 + ty*4 + 2];
            ull a2[8];
            PACK_DUP(a2[0], av0.x); PACK_DUP(a2[1], av0.y);
            PACK_DUP(a2[2], av1.x); PACK_DUP(a2[3], av1.y);
            PACK_DUP(a2[4], av2.x); PACK_DUP(a2[5], av2.y);
            PACK_DUP(a2[6], av3.x); PACK_DUP(a2[7], av3.y);
            #pragma unroll
            for (int i = 0; i < 8; i++)
                #pragma unroll
                for (int p = 0; p < 4; p++)
                    FMA_F32X2(acc2[i][p], a2[i], b2[p]);
        }
        __syncthreads();
    }

    #pragma unroll
    for (int i = 0; i < 8; i++) {
        int o = (i < 4) ? (ty*4 + i) : (64 + ty*4 + (i - 4));
        float d0 = g_d[b*C + o];
        float2 v0 = *(float2*)&acc2[i][0];
        float2 v1 = *(float2*)&acc2[i][1];
        float2 v2 = *(float2*)&acc2[i][2];
        float2 v3 = *(float2*)&acc2[i][3];
        float4 w;
        w.x = v0.x + d0; w.y = v0.y + d0; w.z = v1.x + d0; w.w = v1.y + d0;
        *reinterpret_cast<float4*>(&ob[o*HW + p0 + tx*4]) = w;
        w.x = v2.x + d0; w.y = v2.y + d0; w.z = v3.x + d0; w.w = v3.y + d0;
        *reinterpret_cast<float4*>(&ob[o*HW + p0 + 64 + tx*4]) = w;
    }
}

extern "C" void kernel_launch(void* const* d_in, const int* in_sizes, int n_in,
                              void* d_out, int out_size) {
    const float* x     = (const float*)d_in[0];
    const float* Wsa   = (const float*)d_in[1];
    const float* bsa   = (const float*)d_in[2];
    const float* Wr    = (const float*)d_in[3];
    const float* br    = (const float*)d_in[4];
    const float* kn    = (const float*)d_in[5];
    const float* Wo    = (const float*)d_in[6];
    const float* bo    = (const float*)d_in[7];
    const float* alpha = (const float*)d_in[8];
    const float* sigma = (const float*)d_in[9];
    float* out = (float*)d_out;

    zero_kernel<<<(Bn*C*C + 255) / 256, 256>>>(Wsa);
    gram_kernel<<<dim3(16, Bn), 256>>>(x);
    hgemm_kernel<<<dim3(3, Bn), 256>>>(Wr, Wsa, Wo);
    reduce_kernel<<<dim3(Bn, 8), 128>>>(Wr, Wsa, Wo, kn);
    finalize_kernel<<<Bn, 128>>>(bsa, br, kn, Wo, bo, alpha, sigma);
    loss_kernel<<<1, 256>>>(kn, out, out_size);
    out_kernel<<<dim3(128, Bn), 256>>>(x, out);
}

// round 5
// speedup vs baseline: 1.7628x; 1.1038x over previous
#include <cuda_runtime.h>
#include <math.h>
#include <stdint.h>

#define Bn 8
#define C 128
#define HW 16384
#define Ncls 16
#define EPSF 1e-7f
#define NQ 39
#define KS 16
#define KPC (HW/KS)   // 1024 pixels per gram CTA

// ---------------- tf32 mma.sync helpers (baseline PTX, sm_80+) ----------------
__device__ __forceinline__ uint32_t f2tf32(float v) {
    uint32_t r; asm("cvt.rna.tf32.f32 %0, %1;" : "=r"(r) : "f"(v)); return r;
}
#define MMA_TF32(d, a0,a1,a2,a3, b0,b1) \
    asm volatile("mma.sync.aligned.m16n8k8.row.col.f32.tf32.tf32.f32 " \
        "{%0,%1,%2,%3}, {%4,%5,%6,%7}, {%8,%9}, {%0,%1,%2,%3};" \
        : "+f"((d)[0]), "+f"((d)[1]), "+f"((d)[2]), "+f"((d)[3]) \
        : "r"(a0), "r"(a1), "r"(a2), "r"(a3), "r"(b0), "r"(b1))

// ---------------- scratch ----------------
__device__ float g_G[Bn*C*C];
__device__ float g_sx[Bn*C];
__device__ float g_H[Bn*3*C*C];
__device__ float g_M[Bn*C*C];    // sigma*diag(A)*Wo (NO identity)
__device__ float g_d[Bn*C];
__device__ float g_red[Bn*NQ*C];
__device__ float g_u[C];

// ---------------- zero scratch + compute u ----------------
__global__ void zero_kernel(const float* __restrict__ Wsa) {
    int i = blockIdx.x * blockDim.x + threadIdx.x;
    if (i < Bn*C*C)  g_G[i] = 0.f;
    if (i < Bn*C)    g_sx[i] = 0.f;
    if (i < Bn*NQ*C) g_red[i] = 0.f;
    if (blockIdx.x == 0 && threadIdx.x < C) {
        float u = 0.f;
        #pragma unroll 4
        for (int r = 0; r < C; r++) u += Wsa[r*C + threadIdx.x];
        g_u[threadIdx.x] = u;
    }
}

// ---------------- Gram via mma.sync tf32: G[b] += X X^T ----------------
// grid (KS, Bn), block 256 (8 warps). Warp w: m-strip [w*16, w*16+16), all 128 n.
__global__ __launch_bounds__(256) void gram_mma_kernel(const float* __restrict__ x) {
    const int ks = blockIdx.x;
    const int b  = blockIdx.y;
    const int tid = threadIdx.x;
    const int w = tid >> 5, lane = tid & 31;
    const int gid = lane >> 2, tig = lane & 3;

    __shared__ uint32_t xt[C*36];   // [c][k] pitch 36 (conflict-free frag reads)

    float acc[16][4];
    #pragma unroll
    for (int t = 0; t < 16; t++) { acc[t][0]=0.f; acc[t][1]=0.f; acc[t][2]=0.f; acc[t][3]=0.f; }

    const int c   = tid >> 1;
    const int seg = tid & 1;
    const float* xp = x + ((size_t)b*C + c)*HW + ks*KPC + seg*16;
    float ssum = 0.f;

    for (int it = 0; it < KPC/32; it++) {
        float4 v[4];
        #pragma unroll
        for (int j = 0; j < 4; j++)
            v[j] = *reinterpret_cast<const float4*>(xp + it*32 + j*4);
        // exact fp32 channel sums (pre-conversion)
        #pragma unroll
        for (int j = 0; j < 4; j++) ssum += (v[j].x + v[j].y) + (v[j].z + v[j].w);
        __syncthreads();
        #pragma unroll
        for (int j = 0; j < 4; j++) {
            uint4 u;
            u.x = f2tf32(v[j].x); u.y = f2tf32(v[j].y);
            u.z = f2tf32(v[j].z); u.w = f2tf32(v[j].w);
            *reinterpret_cast<uint4*>(&xt[c*36 + seg*16 + j*4]) = u;
        }
        __syncthreads();
        #pragma unroll
        for (int k8 = 0; k8 < 4; k8++) {
            const int kc = k8*8 + tig;
            uint32_t a0 = xt[(w*16 + gid    )*36 + kc];
            uint32_t a1 = xt[(w*16 + gid + 8)*36 + kc];
            uint32_t a2 = xt[(w*16 + gid    )*36 + kc + 4];
            uint32_t a3 = xt[(w*16 + gid + 8)*36 + kc + 4];
            #pragma unroll
            for (int t = 0; t < 16; t++) {
                uint32_t b0 = xt[(t*8 + gid)*36 + kc];
                uint32_t b1 = xt[(t*8 + gid)*36 + kc + 4];
                MMA_TF32(acc[t], a0, a1, a2, a3, b0, b1);
            }
        }
    }

    float* Gb = g_G + b*C*C;
    const int row0 = w*16 + gid;
    #pragma unroll
    for (int t = 0; t < 16; t++) {
        int col0 = t*8 + 2*tig;
        atomicAdd(&Gb[ row0   *C + col0    ], acc[t][0]);
        atomicAdd(&Gb[ row0   *C + col0 + 1], acc[t][1]);
        atomicAdd(&Gb[(row0+8)*C + col0    ], acc[t][2]);
        atomicAdd(&Gb[(row0+8)*C + col0 + 1], acc[t][3]);
    }
    atomicAdd(&g_sx[b*C + c], ssum);
}

// ---------------- H_m[b] = G[b] @ W_m^T ----------------
__global__ __launch_bounds__(256) void hgemm_kernel(const float* __restrict__ Wr,
                                                    const float* __restrict__ Wsa,
                                                    const float* __restrict__ Wo) {
    const int m = blockIdx.x;
    const int b = blockIdx.y;
    const float* W = (m == 0) ? Wr : (m == 1) ? Wsa : Wo;
    const float* G = g_G + b * C * C;
    float* H = g_H + (b * 3 + m) * C * C;

    __shared__ float As[C][33];
    __shared__ float Bs[C][33];
    const int tid = threadIdx.x;
    const int tx = tid & 15, ty = tid >> 4;
    const int kk = tid & 31, r0w = tid >> 5;

    float accA[4][4] = {}, accB[4][4] = {}, accC[4][4] = {}, accD[4][4] = {};

    for (int k0 = 0; k0 < C; k0 += 32) {
        #pragma unroll
        for (int i = 0; i < 16; i++) {
            int r = r0w + i * 8;
            As[r][kk] = G[r*C + k0 + kk];
            Bs[r][kk] = W[r*C + k0 + kk];
        }
        __syncthreads();
        #pragma unroll 4
        for (int k = 0; k < 32; k++) {
            float a0[4], a1[4], b0[4], b1[4];
            #pragma unroll
            for (int i = 0; i < 4; i++) { a0[i] = As[ty*4+i][k]; a1[i] = As[64+ty*4+i][k]; }
            #pragma unroll
            for (int j = 0; j < 4; j++) { b0[j] = Bs[tx*4+j][k]; b1[j] = Bs[64+tx*4+j][k]; }
            #pragma unroll
            for (int i = 0; i < 4; i++)
                #pragma unroll
                for (int j = 0; j < 4; j++) {
                    accA[i][j] = fmaf(a0[i], b0[j], accA[i][j]);
                    accB[i][j] = fmaf(a0[i], b1[j], accB[i][j]);
                    accC[i][j] = fmaf(a1[i], b0[j], accC[i][j]);
                    accD[i][j] = fmaf(a1[i], b1[j], accD[i][j]);
                }
        }
        __syncthreads();
    }

    #pragma unroll
    for (int i = 0; i < 4; i++) {
        int r0 = ty*4 + i, r1 = 64 + ty*4 + i;
        #pragma unroll
        for (int j = 0; j < 4; j++) {
            int q0 = tx*4 + j, q1 = 64 + tx*4 + j;
            H[r0*C + q0] = accA[i][j];
            H[r0*C + q1] = accB[i][j];
            H[r1*C + q0] = accC[i][j];
            H[r1*C + q1] = accD[i][j];
        }
    }
}

// ---------------- reduce: 39 per-(b,c) reductions over i ----------------
__global__ __launch_bounds__(128) void reduce_kernel(
    const float* __restrict__ Wr, const float* __restrict__ Wsa,
    const float* __restrict__ Wo, const float* __restrict__ kn)
{
    const int b   = blockIdx.x;
    const int i0  = blockIdx.y * 16;
    const int c   = threadIdx.x;
    const float* G  = g_G + b*C*C;
    const float* Hr = g_H + (b*3 + 0)*C*C;
    const float* Hs = g_H + (b*3 + 1)*C*C;
    const float* Ho = g_H + (b*3 + 2)*C*C;

    __shared__ float kn_s[16][Ncls];
    __shared__ float s_s[16], u_s[16];
    {
        int t = threadIdx.x;
        int n = t & 15, ii = t >> 4;
        kn_s[ii][n]     = kn[n*C + i0 + ii];
        kn_s[ii + 8][n] = kn[n*C + i0 + ii + 8];
        if (t < 16) { s_s[t] = g_sx[b*C + i0 + t]; u_s[t] = g_u[i0 + t]; }
    }
    __syncthreads();

    float nxr2 = 0.f, dsa = 0.f, s2v = 0.f, csum = 0.f;
    float wr_s = 0.f, wsa_s = 0.f, wo_s = 0.f;
    float rel[Ncls], P[Ncls];
    #pragma unroll
    for (int n = 0; n < Ncls; n++) { rel[n] = 0.f; P[n] = 0.f; }

    #pragma unroll 4
    for (int ii = 0; ii < 16; ii++) {
        const int i = i0 + ii;
        float hr = Hr[i*C + c];
        float hs = Hs[i*C + c];
        float ho = Ho[i*C + c];
        float g  = G [i*C + c];
        float wri = Wr[c*C + i], wsi = Wsa[c*C + i], woi = Wo[c*C + i];
        float si = s_s[ii], ui = u_s[ii];
        nxr2 = fmaf(wri, hr, nxr2);
        dsa  = fmaf(wsi, hs, dsa);
        s2v  = fmaf(woi, ho, s2v);
        csum = fmaf(ui,  hs, csum);
        wr_s = fmaf(wri, si, wr_s);
        wsa_s= fmaf(wsi, si, wsa_s);
        wo_s = fmaf(woi, si, wo_s);
        #pragma unroll
        for (int n = 0; n < Ncls; n++) {
            float kv = kn_s[ii][n];
            rel[n] = fmaf(kv, hr, rel[n]);
            P[n]   = fmaf(kv, g,  P[n]);
        }
    }

    float* R = g_red + b*NQ*C;
    atomicAdd(&R[0*C + c], nxr2);
    atomicAdd(&R[1*C + c], dsa);
    atomicAdd(&R[2*C + c], s2v);
    atomicAdd(&R[3*C + c], csum);
    atomicAdd(&R[4*C + c], wr_s);
    atomicAdd(&R[5*C + c], wsa_s);
    atomicAdd(&R[6*C + c], wo_s);
    #pragma unroll
    for (int n = 0; n < Ncls; n++) {
        atomicAdd(&R[(7 + n)*C + c],  rel[n]);
        atomicAdd(&R[(23 + n)*C + c], P[n]);
    }
}

// ---------------- finalize ----------------
__global__ __launch_bounds__(128) void finalize_kernel(
    const float* __restrict__ bsa, const float* __restrict__ br,
    const float* __restrict__ kn,
    const float* __restrict__ Wo,  const float* __restrict__ bo,
    const float* __restrict__ alpha, const float* __restrict__ sigma)
{
    const int b = blockIdx.x;
    const int c = threadIdx.x;
    const float* R = g_red + b*NQ*C;
    const float hwf = 16384.f;

    __shared__ float s_sh[C], m_sh[C], s1_sh[C], s2_sh[C], A_sh[C], red_s[C];
    __shared__ float att_sh[Ncls][C];
    __shared__ float pn_sh[Ncls][C];
    __shared__ float nxn_sh[Ncls], kns_sh[Ncls], inv_sh[Ncls], minv_sh[Ncls];
    __shared__ float sc_us, sc_sb, sc_mx, sc_sum;

    float s_c = g_sx[b*C + c];
    s_sh[c] = s_c;
    float u_c = g_u[c];
    float bsc = bsa[c], brc = br[c], boc = bo[c];

    red_s[c] = u_c * s_c;
    __syncthreads();
    #pragma unroll
    for (int s = 64; s > 0; s >>= 1) { if (c < s) red_s[c] += red_s[c + s]; __syncthreads(); }
    if (c == 0) sc_us = red_s[0];
    __syncthreads();
    red_s[c] = bsc;
    __syncthreads();
    #pragma unroll
    for (int s = 64; s > 0; s >>= 1) { if (c < s) red_s[c] += red_s[c + s]; __syncthreads(); }
    if (c == 0) sc_sb = red_s[0];
    __syncthreads();

    #pragma unroll
    for (int n = 0; n < Ncls; n++) pn_sh[n][c] = R[(23 + n)*C + c] * kn[n*C + c];
    __syncthreads();
    if (c < Ncls) {
        float t = 0.f;
        #pragma unroll 4
        for (int k = 0; k < C; k++) t += pn_sh[c][k];
        nxn_sh[c] = sqrtf(t);
    }
    __syncthreads();
    #pragma unroll
    for (int n = 0; n < Ncls; n++) pn_sh[n][c] = kn[n*C + c] * s_sh[c];
    __syncthreads();
    if (c < Ncls) {
        float t = 0.f;
        #pragma unroll 4
        for (int k = 0; k < C; k++) t += pn_sh[c][k];
        kns_sh[c] = t;
    }
    __syncthreads();

    float wr_s = R[4*C + c], wsa_s = R[5*C + c], wo_s = R[6*C + c];
    float nxr2 = R[0*C + c] + 2.f*brc*wr_s + hwf*brc*brc;
    float nxr  = sqrtf(nxr2);
    float dsa  = R[1*C + c] + 2.f*bsc*wsa_s + hwf*bsc*bsc;
    float csum = R[3*C + c] + sc_sb*wsa_s + bsc*sc_us + hwf*sc_sb*bsc;
    m_sh[c]  = (csum - dsa) * (1.f/128.f);
    s1_sh[c] = wo_s + hwf*boc;
    s2_sh[c] = R[2*C + c] + 2.f*boc*wo_s + hwf*boc*boc;
    __syncthreads();

    red_s[c] = m_sh[c];
    __syncthreads();
    #pragma unroll
    for (int s = 64; s > 0; s >>= 1) { if (c < s) red_s[c] = fmaxf(red_s[c], red_s[c + s]); __syncthreads(); }
    if (c == 0) sc_mx = red_s[0];
    __syncthreads();
    float ex = expf(m_sh[c] - sc_mx);
    red_s[c] = ex;
    __syncthreads();
    #pragma unroll
    for (int s = 64; s > 0; s >>= 1) { if (c < s) red_s[c] += red_s[c + s]; __syncthreads(); }
    if (c == 0) sc_sum = red_s[0];
    __syncthreads();
    float regular = ex / sc_sum;

    {
        float rn[Ncls];
        float mxn = -1e30f;
        #pragma unroll
        for (int n = 0; n < Ncls; n++) {
            float r = R[(7 + n)*C + c] + brc * kns_sh[n];
            float al = fminf(fmaxf(alpha[n], 0.f), 1.f);
            rn[n] = r / (nxn_sh[n]*nxr + EPSF) + al * regular;
            mxn = fmaxf(mxn, rn[n]);
        }
        float se = 0.f;
        #pragma unroll
        for (int n = 0; n < Ncls; n++) { rn[n] = expf(rn[n] - mxn); se += rn[n]; }
        float ise = 1.f / se;
        #pragma unroll
        for (int n = 0; n < Ncls; n++) att_sh[n][c] = rn[n] * ise;
    }
    __syncthreads();

    if (c < Ncls) {
        int n = c;
        float cnt = 0.f, hot = 0.f, sq2 = 0.f;
        #pragma unroll 4
        for (int cc = 0; cc < C; cc++) {
            float a = att_sh[n][cc];
            cnt += a;
            hot = fmaf(a, s1_sh[cc], hot);
            sq2 = fmaf(a*a, s2_sh[cc], sq2);
        }
        cnt = cnt * hwf + EPSF;
        float mean = hot / cnt;
        float sq = sq2 - 2.f*mean*hot + mean*mean*(128.f*hwf);
        float stdv = sqrtf(sq / cnt);
        float inv = 1.f / (stdv + EPSF);
        inv_sh[n] = inv; minv_sh[n] = mean * inv;
    }
    __syncthreads();

    float sg = sigma[0];
    {
        float Av = 0.f, Bv = 0.f;
        #pragma unroll
        for (int n = 0; n < Ncls; n++) {
            float a = att_sh[n][c];
            Av = fmaf(a, inv_sh[n],  Av);
            Bv = fmaf(a, minv_sh[n], Bv);
        }
        A_sh[c] = Av;
        g_d[b*C + c] = sg * (Av * boc - Bv);
    }
    __syncthreads();

    // M = sigma*diag(A)*Wo  (identity handled exactly in out epilogue)
    #pragma unroll 4
    for (int t = c; t < C*C; t += 128) {
        int o = t >> 7;
        g_M[b*C*C + t] = sg * A_sh[o] * Wo[t];
    }
}

// ---------------- orthogonality loss ----------------
__global__ void loss_kernel(const float* __restrict__ kn, float* __restrict__ out, int out_size) {
    __shared__ float sym[Ncls][Ncls];
    __shared__ float partial[256];
    int tid = threadIdx.x;
    int i = tid >> 4, j = tid & 15;
    float dot = 0.f;
    #pragma unroll 4
    for (int k = 0; k < C; k++) dot = fmaf(kn[i*C + k], kn[j*C + k], dot);
    sym[i][j] = dot;
    __syncthreads();
    float nr = sqrtf(sym[i][i]) * sqrtf(sym[j][j]);
    float l = sym[i][j] / (nr + EPSF) - (i == j ? 1.f : 0.f);
    partial[tid] = l * l;
    __syncthreads();
    for (int s = 128; s > 0; s >>= 1) {
        if (tid < s) partial[tid] += partial[tid + s];
        __syncthreads();
    }
    if (tid == 0) {
        float loss = 0.1f * logf(partial[0] + 1.f);
        for (int idx = Bn*C*HW; idx < out_size; idx++) out[idx] = loss;
    }
}

// ---------------- out = x + Md@x + d via mma.sync tf32 (3-pass split) ----------------
// grid (HW/128, Bn), block 256.
__global__ __launch_bounds__(256) void out_mma_kernel(const float* __restrict__ x,
                                                      float* __restrict__ out) {
    const int p0 = blockIdx.x * 128;
    const int b  = blockIdx.y;
    const int tid = threadIdx.x;
    const int w = tid >> 5, lane = tid & 31;
    const int gid = lane >> 2, tig = lane & 3;

    // pool: a_hi [128][20] @0, a_lo @2560, x_hi [16][136] @5120, x_lo @7296 (9472 words)
    // epilogue reuses @0 as float stage [128][68] (8704 words)
    __shared__ uint32_t pool[9472];
    uint32_t* a_hi = pool;
    uint32_t* a_lo = pool + 2560;
    uint32_t* xs_hi = pool + 5120;
    uint32_t* xs_lo = pool + 7296;

    const float* Mb = g_M + b*C*C;
    const float* xb = x + (size_t)b*C*HW;

    float acc[16][4];
    #pragma unroll
    for (int t = 0; t < 16; t++) { acc[t][0]=0.f; acc[t][1]=0.f; acc[t][2]=0.f; acc[t][3]=0.f; }

    for (int ch = 0; ch < 8; ch++) {
        const int k0 = ch*16;
        __syncthreads();
        {   // Md chunk [128][16] -> hi/lo
            const int cc = tid >> 1, seg = tid & 1;
            #pragma unroll
            for (int j = 0; j < 2; j++) {
                float4 v = *reinterpret_cast<const float4*>(Mb + cc*C + k0 + seg*8 + j*4);
                uint4 h, l;
                h.x = f2tf32(v.x); l.x = f2tf32(v.x - __uint_as_float(h.x));
                h.y = f2tf32(v.y); l.y = f2tf32(v.y - __uint_as_float(h.y));
                h.z = f2tf32(v.z); l.z = f2tf32(v.z - __uint_as_float(h.z));
                h.w = f2tf32(v.w); l.w = f2tf32(v.w - __uint_as_float(h.w));
                *reinterpret_cast<uint4*>(&a_hi[cc*20 + seg*8 + j*4]) = h;
                *reinterpret_cast<uint4*>(&a_lo[cc*20 + seg*8 + j*4]) = l;
            }
        }
        {   // x chunk [16][128] -> hi/lo
            const int kk = tid >> 4, sg = tid & 15;
            #pragma unroll
            for (int j = 0; j < 2; j++) {
                float4 v = *reinterpret_cast<const float4*>(xb + (size_t)(k0+kk)*HW + p0 + sg*8 + j*4);
                uint4 h, l;
                h.x = f2tf32(v.x); l.x = f2tf32(v.x - __uint_as_float(h.x));
                h.y = f2tf32(v.y); l.y = f2tf32(v.y - __uint_as_float(h.y));
                h.z = f2tf32(v.z); l.z = f2tf32(v.z - __uint_as_float(h.z));
                h.w = f2tf32(v.w); l.w = f2tf32(v.w - __uint_as_float(h.w));
                *reinterpret_cast<uint4*>(&xs_hi[kk*136 + sg*8 + j*4]) = h;
                *reinterpret_cast<uint4*>(&xs_lo[kk*136 + sg*8 + j*4]) = l;
            }
        }
        __syncthreads();
        #pragma unroll
        for (int k8 = 0; k8 < 2; k8++) {
            const int kc = k8*8 + tig;
            uint32_t ah0 = a_hi[(w*16 + gid    )*20 + kc];
            uint32_t ah1 = a_hi[(w*16 + gid + 8)*20 + kc];
            uint32_t ah2 = a_hi[(w*16 + gid    )*20 + kc + 4];
            uint32_t ah3 = a_hi[(w*16 + gid + 8)*20 + kc + 4];
            uint32_t al0 = a_lo[(w*16 + gid    )*20 + kc];
            uint32_t al1 = a_lo[(w*16 + gid + 8)*20 + kc];
            uint32_t al2 = a_lo[(w*16 + gid    )*20 + kc + 4];
            uint32_t al3 = a_lo[(w*16 + gid + 8)*20 + kc + 4];
            #pragma unroll
            for (int t = 0; t < 16; t++) {
                uint32_t bh0 = xs_hi[ kc   *136 + t*8 + gid];
                uint32_t bh1 = xs_hi[(kc+4)*136 + t*8 + gid];
                uint32_t bl0 = xs_lo[ kc   *136 + t*8 + gid];
                uint32_t bl1 = xs_lo[(kc+4)*136 + t*8 + gid];
                MMA_TF32(acc[t], ah0, ah1, ah2, ah3, bh0, bh1);
                MMA_TF32(acc[t], ah0, ah1, ah2, ah3, bl0, bl1);
                MMA_TF32(acc[t], al0, al1, al2, al3, bh0, bh1);
            }
        }
    }

    // epilogue: out = x + delta + d  (two 64-col halves staged through smem)
    float* stage = reinterpret_cast<float*>(pool);
    float* ob = out + (size_t)b*C*HW;
    const int cc = tid >> 1, sg2 = tid & 1;
    const float dc = g_d[b*C + cc];
    #pragma unroll
    for (int half = 0; half < 2; half++) {
        __syncthreads();
        #pragma unroll
        for (int t = 0; t < 8; t++) {
            int tt = half*8 + t;
            int colL = t*8 + 2*tig;
            stage[(w*16 + gid    )*68 + colL    ] = acc[tt][0];
            stage[(w*16 + gid    )*68 + colL + 1] = acc[tt][1];
            stage[(w*16 + gid + 8)*68 + colL    ] = acc[tt][2];
            stage[(w*16 + gid + 8)*68 + colL + 1] = acc[tt][3];
        }
        __syncthreads();
        #pragma unroll
        for (int j = 0; j < 8; j++) {
            int p = sg2*32 + j*4;
            float4 xv = *reinterpret_cast<const float4*>(xb + (size_t)cc*HW + p0 + half*64 + p);
            float4 sv = *reinterpret_cast<const float4*>(&stage[cc*68 + p]);
            float4 o;
            o.x = xv.x + sv.x + dc;
            o.y = xv.y + sv.y + dc;
            o.z = xv.z + sv.z + dc;
            o.w = xv.w + sv.w + dc;
            *reinterpret_cast<float4*>(ob + (size_t)cc*HW + p0 + half*64 + p) = o;
        }
    }
}

extern "C" void kernel_launch(void* const* d_in, const int* in_sizes, int n_in,
                              void* d_out, int out_size) {
    const float* x     = (const float*)d_in[0];
    const float* Wsa   = (const float*)d_in[1];
    const float* bsa   = (const float*)d_in[2];
    const float* Wr    = (const float*)d_in[3];
    const float* br    = (const float*)d_in[4];
    const float* kn    = (const float*)d_in[5];
    const float* Wo    = (const float*)d_in[6];
    const float* bo    = (const float*)d_in[7];
    const float* alpha = (const float*)d_in[8];
    const float* sigma = (const float*)d_in[9];
    float* out = (float*)d_out;

    zero_kernel<<<(Bn*C*C + 255) / 256, 256>>>(Wsa);
    gram_mma_kernel<<<dim3(KS, Bn), 256>>>(x);
    hgemm_kernel<<<dim3(3, Bn), 256>>>(Wr, Wsa, Wo);
    reduce_kernel<<<dim3(Bn, 8), 128>>>(Wr, Wsa, Wo, kn);
    finalize_kernel<<<Bn, 128>>>(bsa, br, kn, Wo, bo, alpha, sigma);
    loss_kernel<<<1, 256>>>(kn, out, out_size);
    out_mma_kernel<<<dim3(HW/128, Bn), 256>>>(x, out);
}